// round 4
// baseline (speedup 1.0000x reference)
#include <cuda_runtime.h>

// Problem constants
#define E_   1024
#define H_   16
#define D_   64
#define B_   4
#define NQ_  4096
#define NK_  4096
#define MTOT (B_*NQ_)      // 16384 rows for all projections
#define BH_  (B_*H_)       // 64
#define NSPLIT 32          // split-K partitions for KV reduction

// ---------------- scratch (device globals; no allocation APIs) ----------------
__device__ float g_q[(size_t)MTOT * E_];      // 64 MiB
__device__ float g_k[(size_t)MTOT * E_];      // 64 MiB
__device__ float g_v[(size_t)MTOT * E_];      // 64 MiB
__device__ float g_attn[(size_t)MTOT * E_];   // 64 MiB
__device__ float g_kvp[(size_t)NSPLIT * BH_ * D_ * D_];  // 32 MiB partials
__device__ float g_ksp[(size_t)NSPLIT * BH_ * D_];       // 0.5 MiB partials
__device__ float g_kv[(size_t)BH_ * D_ * D_];            // 1 MiB
__device__ float g_ksum[(size_t)BH_ * D_];

// ---------------- GEMM: C[m,n] = sum_k X[m,k]*W[n,k] + bias[n] ----------------
// X: [MTOT, E], W: [E, E] row-major (torch Linear weight), C: [MTOT, E]
// 128x128 block tile, 16 k-tile double-buffered, 256 threads, 8x8 micro tile.
__global__ __launch_bounds__(256)
void gemm_bias_kernel(const float* __restrict__ X, const float* __restrict__ W,
                      const float* __restrict__ bias, float* __restrict__ C) {
    __shared__ float As[2][16][132];
    __shared__ float Bs[2][16][132];

    const int t  = threadIdx.x;
    const int bm = blockIdx.x * 128;
    const int bn = blockIdx.y * 128;
    const int tx = t & 15;          // 0..15 -> 8 output cols
    const int ty = t >> 4;          // 0..15 -> 8 output rows
    const int lr = t >> 2;          // 0..63 load row
    const int lc = (t & 3) * 4;     // 0,4,8,12 load col (k)

    float acc[8][8];
#pragma unroll
    for (int i = 0; i < 8; i++)
#pragma unroll
        for (int j = 0; j < 8; j++) acc[i][j] = 0.0f;

    float4 xa[2], wb[2];

    // initial load of K-tile 0 into buffer 0
#pragma unroll
    for (int i = 0; i < 2; i++) {
        int r = lr + i * 64;
        xa[i] = *(const float4*)(X + (size_t)(bm + r) * E_ + lc);
        wb[i] = *(const float4*)(W + (size_t)(bn + r) * E_ + lc);
    }
#pragma unroll
    for (int i = 0; i < 2; i++) {
        int r = lr + i * 64;
        As[0][lc + 0][r] = xa[i].x; As[0][lc + 1][r] = xa[i].y;
        As[0][lc + 2][r] = xa[i].z; As[0][lc + 3][r] = xa[i].w;
        Bs[0][lc + 0][r] = wb[i].x; Bs[0][lc + 1][r] = wb[i].y;
        Bs[0][lc + 2][r] = wb[i].z; Bs[0][lc + 3][r] = wb[i].w;
    }
    __syncthreads();

    int buf = 0;
    for (int k0 = 0; k0 < E_; k0 += 16) {
        const bool has_next = (k0 + 16) < E_;
        // prefetch next K-tile into registers (overlaps with compute below)
        if (has_next) {
#pragma unroll
            for (int i = 0; i < 2; i++) {
                int r = lr + i * 64;
                xa[i] = *(const float4*)(X + (size_t)(bm + r) * E_ + k0 + 16 + lc);
                wb[i] = *(const float4*)(W + (size_t)(bn + r) * E_ + k0 + 16 + lc);
            }
        }
        // compute on current buffer
#pragma unroll
        for (int k = 0; k < 16; k++) {
            float a[8], b[8];
            *(float4*)(a)     = *(const float4*)&As[buf][k][ty * 8];
            *(float4*)(a + 4) = *(const float4*)&As[buf][k][ty * 8 + 4];
            *(float4*)(b)     = *(const float4*)&Bs[buf][k][tx * 8];
            *(float4*)(b + 4) = *(const float4*)&Bs[buf][k][tx * 8 + 4];
#pragma unroll
            for (int i = 0; i < 8; i++)
#pragma unroll
                for (int j = 0; j < 8; j++)
                    acc[i][j] += a[i] * b[j];
        }
        // store prefetched tile into the other buffer
        if (has_next) {
            int nb = buf ^ 1;
#pragma unroll
            for (int i = 0; i < 2; i++) {
                int r = lr + i * 64;
                As[nb][lc + 0][r] = xa[i].x; As[nb][lc + 1][r] = xa[i].y;
                As[nb][lc + 2][r] = xa[i].z; As[nb][lc + 3][r] = xa[i].w;
                Bs[nb][lc + 0][r] = wb[i].x; Bs[nb][lc + 1][r] = wb[i].y;
                Bs[nb][lc + 2][r] = wb[i].z; Bs[nb][lc + 3][r] = wb[i].w;
            }
        }
        __syncthreads();
        buf ^= 1;
    }

#pragma unroll
    for (int i = 0; i < 8; i++) {
        int row = bm + ty * 8 + i;
#pragma unroll
        for (int j = 0; j < 8; j += 4) {
            int col = bn + tx * 8 + j;
            float4 o;
            o.x = acc[i][j + 0] + bias[col + 0];
            o.y = acc[i][j + 1] + bias[col + 1];
            o.z = acc[i][j + 2] + bias[col + 2];
            o.w = acc[i][j + 3] + bias[col + 3];
            *(float4*)(C + (size_t)row * E_ + col) = o;
        }
    }
}

// ---------------- LayerNorm + elu + 1, in place, one block per row ----------------
__global__ __launch_bounds__(256)
void ln_elu_kernel(float* __restrict__ X, const float* __restrict__ gamma,
                   const float* __restrict__ beta) {
    const int row = blockIdx.x;
    const int t = threadIdx.x;
    float* xr = X + (size_t)row * E_;

    float v[4];
#pragma unroll
    for (int i = 0; i < 4; i++) v[i] = xr[t + i * 256];

    __shared__ float red[8];
    // mean
    float s = v[0] + v[1] + v[2] + v[3];
#pragma unroll
    for (int o = 16; o > 0; o >>= 1) s += __shfl_xor_sync(0xffffffffu, s, o);
    if ((t & 31) == 0) red[t >> 5] = s;
    __syncthreads();
    float tot = red[0] + red[1] + red[2] + red[3] + red[4] + red[5] + red[6] + red[7];
    float mean = tot * (1.0f / E_);
    __syncthreads();

    // variance
    float d0 = v[0] - mean, d1 = v[1] - mean, d2 = v[2] - mean, d3 = v[3] - mean;
    float s2 = d0 * d0 + d1 * d1 + d2 * d2 + d3 * d3;
#pragma unroll
    for (int o = 16; o > 0; o >>= 1) s2 += __shfl_xor_sync(0xffffffffu, s2, o);
    if ((t & 31) == 0) red[t >> 5] = s2;
    __syncthreads();
    float var = (red[0] + red[1] + red[2] + red[3] + red[4] + red[5] + red[6] + red[7]) * (1.0f / E_);
    float rstd = rsqrtf(var + 1e-5f);

    float dd[4] = {d0, d1, d2, d3};
#pragma unroll
    for (int i = 0; i < 4; i++) {
        int col = t + i * 256;
        float y = dd[i] * rstd * gamma[col] + beta[col];
        // elu(y)+1:  y>0 ? y+1 : exp(y)
        xr[col] = (y > 0.0f) ? (y + 1.0f) : expf(y);
    }
}

// ---------------- KV reduction: per (b,h), split over N ----------------
// kv[d][e] = sum_n K[n][d]*V[n][e]; ksum[d] = sum_n K[n][d]
// grid (BH, NSPLIT), 256 threads. Writes deterministic partials.
__global__ __launch_bounds__(256)
void kv_kernel() {
    const int bh = blockIdx.x;
    const int b = bh >> 4, h = bh & 15;
    const int split = blockIdx.y;
    const int t = threadIdx.x;
    const int tx = t & 15, ty = t >> 4;

    __shared__ float Ks[64][68];
    __shared__ float Vs[64][68];

    const float* kbase = g_k + (size_t)(b * NK_) * E_ + h * D_;
    const float* vbase = g_v + (size_t)(b * NK_) * E_ + h * D_;

    float acc[4][4];
#pragma unroll
    for (int i = 0; i < 4; i++)
#pragma unroll
        for (int j = 0; j < 4; j++) acc[i][j] = 0.0f;
    float ks_local = 0.0f;

    for (int sblk = 0; sblk < 2; sblk++) {
        int n0 = split * 128 + sblk * 64;
#pragma unroll
        for (int l = 0; l < 4; l++) {
            int lin = t + l * 256;           // 0..1023
            int r = lin >> 4;                // 0..63
            int c4 = (lin & 15) * 4;         // 0..60
            *(float4*)&Ks[r][c4] = *(const float4*)(kbase + (size_t)(n0 + r) * E_ + c4);
            *(float4*)&Vs[r][c4] = *(const float4*)(vbase + (size_t)(n0 + r) * E_ + c4);
        }
        __syncthreads();
#pragma unroll 4
        for (int n = 0; n < 64; n++) {
            float a[4], bb[4];
            *(float4*)a  = *(const float4*)&Ks[n][ty * 4];
            *(float4*)bb = *(const float4*)&Vs[n][tx * 4];
#pragma unroll
            for (int i = 0; i < 4; i++)
#pragma unroll
                for (int j = 0; j < 4; j++)
                    acc[i][j] += a[i] * bb[j];
        }
        if (t < 64) {
            float ss = 0.0f;
#pragma unroll 4
            for (int n = 0; n < 64; n++) ss += Ks[n][t];
            ks_local += ss;
        }
        __syncthreads();
    }

    float* outp = g_kvp + ((size_t)(split * BH_ + bh)) * (D_ * D_);
#pragma unroll
    for (int i = 0; i < 4; i++)
#pragma unroll
        for (int j = 0; j < 4; j++)
            outp[(ty * 4 + i) * D_ + tx * 4 + j] = acc[i][j];
    if (t < 64) g_ksp[(size_t)(split * BH_ + bh) * D_ + t] = ks_local;
}

// ---------------- reduce split-K partials ----------------
__global__ __launch_bounds__(256)
void reduce_kv_kernel() {
    int idx = blockIdx.x * blockDim.x + threadIdx.x;
    const int NKV = BH_ * D_ * D_;   // 262144
    const int NKS = BH_ * D_;        // 4096
    if (idx < NKV) {
        float s = 0.0f;
#pragma unroll
        for (int sp = 0; sp < NSPLIT; sp++)
            s += g_kvp[(size_t)sp * NKV + idx];
        g_kv[idx] = s;
    } else if (idx < NKV + NKS) {
        int j = idx - NKV;
        float s = 0.0f;
#pragma unroll
        for (int sp = 0; sp < NSPLIT; sp++)
            s += g_ksp[(size_t)sp * NKS + j];
        g_ksum[j] = s;
    }
}

// ---------------- attention apply: num = Q @ KV, den = Q . ksum, out = num/den ----
// grid (BH, NQ/64), 128 threads; block handles 64 query rows of one (b,h).
__global__ __launch_bounds__(128)
void attn_kernel() {
    const int bh = blockIdx.x;
    const int b = bh >> 4, h = bh & 15;
    const int n0 = blockIdx.y * 64;
    const int t = threadIdx.x;

    __shared__ float Qs[64][68];
    __shared__ float KVs[64][68];
    __shared__ float ksums[64];

#pragma unroll
    for (int l = 0; l < 8; l++) {
        int lin = t + l * 128;           // 0..1023
        int r = lin >> 4;
        int c4 = (lin & 15) * 4;
        *(float4*)&KVs[r][c4] = *(const float4*)(g_kv + (size_t)bh * (D_ * D_) + r * D_ + c4);
        *(float4*)&Qs[r][c4]  = *(const float4*)(g_q + (size_t)(b * NQ_ + n0 + r) * E_ + h * D_ + c4);
    }
    if (t < 64) ksums[t] = g_ksum[(size_t)bh * D_ + t];
    __syncthreads();

    const int tx = t & 15;   // 4 cols
    const int ty = t >> 4;   // 0..7 -> 8 rows
    float acc[8][4];
#pragma unroll
    for (int i = 0; i < 8; i++)
#pragma unroll
        for (int j = 0; j < 4; j++) acc[i][j] = 0.0f;

#pragma unroll 4
    for (int d = 0; d < 64; d++) {
        float bb[4];
        *(float4*)bb = *(const float4*)&KVs[d][tx * 4];
#pragma unroll
        for (int i = 0; i < 8; i++) {
            float a = Qs[ty * 8 + i][d];
#pragma unroll
            for (int j = 0; j < 4; j++) acc[i][j] += a * bb[j];
        }
    }

    float den[8];
#pragma unroll
    for (int i = 0; i < 8; i++) den[i] = 0.0f;
#pragma unroll 4
    for (int d = 0; d < 64; d++) {
        float kd = ksums[d];
#pragma unroll
        for (int i = 0; i < 8; i++) den[i] += Qs[ty * 8 + i][d] * kd;
    }

#pragma unroll
    for (int i = 0; i < 8; i++) {
        float inv = 1.0f / (den[i] + 1e-8f);
        int row = b * NQ_ + n0 + ty * 8 + i;
        float4 o;
        o.x = acc[i][0] * inv; o.y = acc[i][1] * inv;
        o.z = acc[i][2] * inv; o.w = acc[i][3] * inv;
        *(float4*)(g_attn + (size_t)row * E_ + h * D_ + tx * 4) = o;
    }
}

// ---------------- host launcher ----------------
extern "C" void kernel_launch(void* const* d_in, const int* in_sizes, int n_in,
                              void* d_out, int out_size) {
    (void)in_sizes; (void)n_in; (void)out_size;
    const float* query = (const float*)d_in[0];
    const float* key   = (const float*)d_in[1];
    const float* value = (const float*)d_in[2];
    const float* Wq = (const float*)d_in[3];
    const float* bq = (const float*)d_in[4];
    const float* Wk = (const float*)d_in[5];
    const float* bk = (const float*)d_in[6];
    const float* Wv = (const float*)d_in[7];
    const float* bv = (const float*)d_in[8];
    const float* Wo = (const float*)d_in[9];
    const float* bo = (const float*)d_in[10];
    const float* gq    = (const float*)d_in[11];
    const float* betaq = (const float*)d_in[12];
    const float* gk    = (const float*)d_in[13];
    const float* betak = (const float*)d_in[14];
    float* out = (float*)d_out;

    float *pq, *pk, *pv, *pattn;
    cudaGetSymbolAddress((void**)&pq, g_q);
    cudaGetSymbolAddress((void**)&pk, g_k);
    cudaGetSymbolAddress((void**)&pv, g_v);
    cudaGetSymbolAddress((void**)&pattn, g_attn);

    dim3 ggrid(MTOT / 128, E_ / 128);   // (128, 8)

    // Q projection + LN + elu+1
    gemm_bias_kernel<<<ggrid, 256>>>(query, Wq, bq, pq);
    ln_elu_kernel<<<MTOT, 256>>>(pq, gq, betaq);
    // K projection + LN + elu+1
    gemm_bias_kernel<<<ggrid, 256>>>(key, Wk, bk, pk);
    ln_elu_kernel<<<MTOT, 256>>>(pk, gk, betak);
    // V projection
    gemm_bias_kernel<<<ggrid, 256>>>(value, Wv, bv, pv);

    // KV / ksum reduction (split-K partials, then deterministic reduce)
    kv_kernel<<<dim3(BH_, NSPLIT), 256>>>();
    reduce_kv_kernel<<<(BH_ * D_ * D_ + BH_ * D_ + 255) / 256, 256>>>();

    // attention apply
    attn_kernel<<<dim3(BH_, NQ_ / 64), 128>>>();

    // output projection -> d_out
    gemm_bias_kernel<<<ggrid, 256>>>(pattn, Wo, bo, out);
}

// round 7
// speedup vs baseline: 2.9062x; 2.9062x over previous
#include <cuda_runtime.h>
#include <cstdint>

// Problem constants
#define E_   1024
#define H_   16
#define D_   64
#define B_   4
#define NQ_  4096
#define NK_  4096
#define MTOT (B_*NQ_)      // 16384 rows for all projections
#define BH_  (B_*H_)       // 64
#define NSPLIT 32          // split-K partitions for KV reduction

// ---------------- scratch (device globals; no allocation APIs) ----------------
__device__ float g_q[(size_t)MTOT * E_];      // 64 MiB
__device__ float g_k[(size_t)MTOT * E_];      // 64 MiB
__device__ float g_v[(size_t)MTOT * E_];      // 64 MiB
__device__ float g_attn[(size_t)MTOT * E_];   // 64 MiB
__device__ float g_kvp[(size_t)NSPLIT * BH_ * D_ * D_];  // 32 MiB partials
__device__ float g_ksp[(size_t)NSPLIT * BH_ * D_];       // 0.5 MiB partials
__device__ float g_kv[(size_t)BH_ * D_ * D_];            // 1 MiB
__device__ float g_ksum[(size_t)BH_ * D_];

// =====================================================================
// Helpers: cp.async (sm_80+ base target, no 'a' features needed)
// =====================================================================
__device__ __forceinline__ uint32_t smem_u32(const void* p) {
    uint32_t a;
    asm("{ .reg .u64 t; cvta.to.shared.u64 t, %1; cvt.u32.u64 %0, t; }"
        : "=r"(a) : "l"(p));
    return a;
}

__device__ __forceinline__ void cp_async16(uint32_t saddr, const void* gaddr) {
    asm volatile("cp.async.cg.shared.global [%0], [%1], 16;"
                 :: "r"(saddr), "l"(gaddr));
}
__device__ __forceinline__ void cp_commit() {
    asm volatile("cp.async.commit_group;" ::: "memory");
}
template <int N>
__device__ __forceinline__ void cp_wait() {
    asm volatile("cp.async.wait_group %0;" :: "n"(N) : "memory");
}

__device__ __forceinline__ uint32_t f2tf32(float f) {
    uint32_t u;
    asm("cvt.rna.tf32.f32 %0, %1;" : "=r"(u) : "f"(f));
    return u;
}

// D(16x8,f32) += A(16x8,tf32,row) * B(8x8,tf32,col)
__device__ __forceinline__ void mma_tf32(
    float& d0, float& d1, float& d2, float& d3,
    uint32_t a0, uint32_t a1, uint32_t a2, uint32_t a3,
    uint32_t b0, uint32_t b1)
{
    asm volatile(
        "mma.sync.aligned.m16n8k8.row.col.f32.tf32.tf32.f32 "
        "{%0,%1,%2,%3}, {%4,%5,%6,%7}, {%8,%9}, {%0,%1,%2,%3};"
        : "+f"(d0), "+f"(d1), "+f"(d2), "+f"(d3)
        : "r"(a0), "r"(a1), "r"(a2), "r"(a3), "r"(b0), "r"(b1));
}

// =====================================================================
// tf32 tensor-core GEMM:  C[m,n] = sum_k X[m,k]*W[n,k] + bias[n]
// 128x128 CTA tile, BK=32, cp.async double buffer, 256 threads (8 warps 2x4),
// warp tile 64x32 (4 mfrag x 4 nfrag of m16n8k8).
// =====================================================================
#define BM 128
#define BN 128
#define BK 32
#define NKT (E_/BK)        // 32 k-tiles
#define ASTR 36            // smem row stride in floats (bank-conflict-free)
#define TILEF (128*ASTR)   // 4608 floats = 18432 B per tile buffer
#define GEMM_SMEM (4*TILEF*4)   // A0,A1,B0,B1 = 73728 bytes

__global__ void __launch_bounds__(256, 2)
gemm_mma_kernel(const float* __restrict__ X, const float* __restrict__ W,
                const float* __restrict__ bias, float* __restrict__ C)
{
    extern __shared__ float smf[];
    const uint32_t sbase = smem_u32(smf);
    const int tid = threadIdx.x;
    const int wid = tid >> 5;
    const int lane = tid & 31;
    const int g  = lane >> 2;       // 0..7
    const int t4 = lane & 3;        // 0..3
    const int wm = (wid >> 2) * 64; // warp M offset: 0 or 64
    const int wn = (wid & 3) * 32;  // warp N offset: 0,32,64,96
    const int bm = blockIdx.x * BM;
    const int bn = blockIdx.y * BN;

    // per-thread staging coords: 4 chunks of 16B for A, 4 for B
    const int srow = tid >> 3;          // 0..31 (row block per l-iter adds 32)
    const int sc4  = (tid & 7) * 4;     // 0,4,...,28

    float acc[4][4][4];
#pragma unroll
    for (int i = 0; i < 4; i++)
#pragma unroll
        for (int j = 0; j < 4; j++)
#pragma unroll
            for (int r = 0; r < 4; r++) acc[i][j][r] = 0.0f;

    // prefetch k-tile kt into buffer buf
    auto prefetch = [&](int kt, int buf) {
        const int k0 = kt * BK;
        const uint32_t aoff = sbase + (uint32_t)(buf * TILEF) * 4u;
        const uint32_t boff = sbase + (uint32_t)((2 + buf) * TILEF) * 4u;
#pragma unroll
        for (int l = 0; l < 4; l++) {
            int row = srow + l * 32;
            cp_async16(aoff + (row * ASTR + sc4) * 4,
                       X + (size_t)(bm + row) * E_ + k0 + sc4);
            cp_async16(boff + (row * ASTR + sc4) * 4,
                       W + (size_t)(bn + row) * E_ + k0 + sc4);
        }
        cp_commit();
    };

    prefetch(0, 0);

    for (int kt = 0; kt < NKT; kt++) {
        const int buf = kt & 1;
        if (kt + 1 < NKT) {
            prefetch(kt + 1, buf ^ 1);
            cp_wait<1>();
        } else {
            cp_wait<0>();
        }
        __syncthreads();

        const float* As = smf + buf * TILEF;
        const float* Bs = smf + (2 + buf) * TILEF;

#pragma unroll
        for (int ks = 0; ks < 4; ks++) {
            const int kk = ks * 8;
            // B fragments: 4 nfrags x 2 regs
            uint32_t bf[4][2];
#pragma unroll
            for (int nf = 0; nf < 4; nf++) {
                const float* bp = Bs + (wn + nf * 8 + g) * ASTR + kk + t4;
                bf[nf][0] = f2tf32(bp[0]);
                bf[nf][1] = f2tf32(bp[4]);
            }
#pragma unroll
            for (int mf = 0; mf < 4; mf++) {
                const float* ap = As + (wm + mf * 16 + g) * ASTR + kk + t4;
                uint32_t a0 = f2tf32(ap[0]);
                uint32_t a1 = f2tf32(ap[8 * ASTR]);
                uint32_t a2 = f2tf32(ap[4]);
                uint32_t a3 = f2tf32(ap[8 * ASTR + 4]);
#pragma unroll
                for (int nf = 0; nf < 4; nf++)
                    mma_tf32(acc[mf][nf][0], acc[mf][nf][1],
                             acc[mf][nf][2], acc[mf][nf][3],
                             a0, a1, a2, a3, bf[nf][0], bf[nf][1]);
            }
        }
        __syncthreads();
    }

    // Epilogue: bias add + direct stores (float2 per row-pair)
#pragma unroll
    for (int nf = 0; nf < 4; nf++) {
        const int col = bn + wn + nf * 8 + t4 * 2;
        const float2 b2 = *(const float2*)(bias + col);
#pragma unroll
        for (int mf = 0; mf < 4; mf++) {
            const int row0 = bm + wm + mf * 16 + g;
            float2 v0, v1;
            v0.x = acc[mf][nf][0] + b2.x;
            v0.y = acc[mf][nf][1] + b2.y;
            v1.x = acc[mf][nf][2] + b2.x;
            v1.y = acc[mf][nf][3] + b2.y;
            *(float2*)(C + (size_t)row0 * E_ + col) = v0;
            *(float2*)(C + (size_t)(row0 + 8) * E_ + col) = v1;
        }
    }
}

// ---------------- LayerNorm + elu + 1, in place, one block per row ----------------
__global__ __launch_bounds__(256)
void ln_elu_kernel(float* __restrict__ X, const float* __restrict__ gamma,
                   const float* __restrict__ beta) {
    const int row = blockIdx.x;
    const int t = threadIdx.x;
    float* xr = X + (size_t)row * E_;

    float v[4];
#pragma unroll
    for (int i = 0; i < 4; i++) v[i] = xr[t + i * 256];

    __shared__ float red[8];
    float s = v[0] + v[1] + v[2] + v[3];
#pragma unroll
    for (int o = 16; o > 0; o >>= 1) s += __shfl_xor_sync(0xffffffffu, s, o);
    if ((t & 31) == 0) red[t >> 5] = s;
    __syncthreads();
    float tot = red[0] + red[1] + red[2] + red[3] + red[4] + red[5] + red[6] + red[7];
    float mean = tot * (1.0f / E_);
    __syncthreads();

    float d0 = v[0] - mean, d1 = v[1] - mean, d2 = v[2] - mean, d3 = v[3] - mean;
    float s2 = d0 * d0 + d1 * d1 + d2 * d2 + d3 * d3;
#pragma unroll
    for (int o = 16; o > 0; o >>= 1) s2 += __shfl_xor_sync(0xffffffffu, s2, o);
    if ((t & 31) == 0) red[t >> 5] = s2;
    __syncthreads();
    float var = (red[0] + red[1] + red[2] + red[3] + red[4] + red[5] + red[6] + red[7]) * (1.0f / E_);
    float rstd = rsqrtf(var + 1e-5f);

    float dd[4] = {d0, d1, d2, d3};
#pragma unroll
    for (int i = 0; i < 4; i++) {
        int col = t + i * 256;
        float y = dd[i] * rstd * gamma[col] + beta[col];
        xr[col] = (y > 0.0f) ? (y + 1.0f) : expf(y);
    }
}

// ---------------- KV reduction: per (b,h), split over N ----------------
__global__ __launch_bounds__(256)
void kv_kernel() {
    const int bh = blockIdx.x;
    const int b = bh >> 4, h = bh & 15;
    const int split = blockIdx.y;
    const int t = threadIdx.x;
    const int tx = t & 15, ty = t >> 4;

    __shared__ float Ks[64][68];
    __shared__ float Vs[64][68];

    const float* kbase = g_k + (size_t)(b * NK_) * E_ + h * D_;
    const float* vbase = g_v + (size_t)(b * NK_) * E_ + h * D_;

    float acc[4][4];
#pragma unroll
    for (int i = 0; i < 4; i++)
#pragma unroll
        for (int j = 0; j < 4; j++) acc[i][j] = 0.0f;
    float ks_local = 0.0f;

    for (int sblk = 0; sblk < 2; sblk++) {
        int n0 = split * 128 + sblk * 64;
#pragma unroll
        for (int l = 0; l < 4; l++) {
            int lin = t + l * 256;
            int r = lin >> 4;
            int c4 = (lin & 15) * 4;
            *(float4*)&Ks[r][c4] = *(const float4*)(kbase + (size_t)(n0 + r) * E_ + c4);
            *(float4*)&Vs[r][c4] = *(const float4*)(vbase + (size_t)(n0 + r) * E_ + c4);
        }
        __syncthreads();
#pragma unroll 4
        for (int n = 0; n < 64; n++) {
            float a[4], bb[4];
            *(float4*)a  = *(const float4*)&Ks[n][ty * 4];
            *(float4*)bb = *(const float4*)&Vs[n][tx * 4];
#pragma unroll
            for (int i = 0; i < 4; i++)
#pragma unroll
                for (int j = 0; j < 4; j++)
                    acc[i][j] += a[i] * bb[j];
        }
        if (t < 64) {
            float ss = 0.0f;
#pragma unroll 4
            for (int n = 0; n < 64; n++) ss += Ks[n][t];
            ks_local += ss;
        }
        __syncthreads();
    }

    float* outp = g_kvp + ((size_t)(split * BH_ + bh)) * (D_ * D_);
#pragma unroll
    for (int i = 0; i < 4; i++)
#pragma unroll
        for (int j = 0; j < 4; j++)
            outp[(ty * 4 + i) * D_ + tx * 4 + j] = acc[i][j];
    if (t < 64) g_ksp[(size_t)(split * BH_ + bh) * D_ + t] = ks_local;
}

// ---------------- reduce split-K partials ----------------
__global__ __launch_bounds__(256)
void reduce_kv_kernel() {
    int idx = blockIdx.x * blockDim.x + threadIdx.x;
    const int NKV = BH_ * D_ * D_;
    const int NKS = BH_ * D_;
    if (idx < NKV) {
        float s = 0.0f;
#pragma unroll
        for (int sp = 0; sp < NSPLIT; sp++)
            s += g_kvp[(size_t)sp * NKV + idx];
        g_kv[idx] = s;
    } else if (idx < NKV + NKS) {
        int j = idx - NKV;
        float s = 0.0f;
#pragma unroll
        for (int sp = 0; sp < NSPLIT; sp++)
            s += g_ksp[(size_t)sp * NKS + j];
        g_ksum[j] = s;
    }
}

// ---------------- attention apply ----------------
__global__ __launch_bounds__(128)
void attn_kernel() {
    const int bh = blockIdx.x;
    const int b = bh >> 4, h = bh & 15;
    const int n0 = blockIdx.y * 64;
    const int t = threadIdx.x;

    __shared__ float Qs[64][68];
    __shared__ float KVs[64][68];
    __shared__ float ksums[64];

#pragma unroll
    for (int l = 0; l < 8; l++) {
        int lin = t + l * 128;
        int r = lin >> 4;
        int c4 = (lin & 15) * 4;
        *(float4*)&KVs[r][c4] = *(const float4*)(g_kv + (size_t)bh * (D_ * D_) + r * D_ + c4);
        *(float4*)&Qs[r][c4]  = *(const float4*)(g_q + (size_t)(b * NQ_ + n0 + r) * E_ + h * D_ + c4);
    }
    if (t < 64) ksums[t] = g_ksum[(size_t)bh * D_ + t];
    __syncthreads();

    const int tx = t & 15;
    const int ty = t >> 4;
    float acc[8][4];
#pragma unroll
    for (int i = 0; i < 8; i++)
#pragma unroll
        for (int j = 0; j < 4; j++) acc[i][j] = 0.0f;

#pragma unroll 4
    for (int d = 0; d < 64; d++) {
        float bb[4];
        *(float4*)bb = *(const float4*)&KVs[d][tx * 4];
#pragma unroll
        for (int i = 0; i < 8; i++) {
            float a = Qs[ty * 8 + i][d];
#pragma unroll
            for (int j = 0; j < 4; j++) acc[i][j] += a * bb[j];
        }
    }

    float den[8];
#pragma unroll
    for (int i = 0; i < 8; i++) den[i] = 0.0f;
#pragma unroll 4
    for (int d = 0; d < 64; d++) {
        float kd = ksums[d];
#pragma unroll
        for (int i = 0; i < 8; i++) den[i] += Qs[ty * 8 + i][d] * kd;
    }

#pragma unroll
    for (int i = 0; i < 8; i++) {
        float inv = 1.0f / (den[i] + 1e-8f);
        int row = b * NQ_ + n0 + ty * 8 + i;
        float4 o;
        o.x = acc[i][0] * inv; o.y = acc[i][1] * inv;
        o.z = acc[i][2] * inv; o.w = acc[i][3] * inv;
        *(float4*)(g_attn + (size_t)row * E_ + h * D_ + tx * 4) = o;
    }
}

// ---------------- host launcher ----------------
extern "C" void kernel_launch(void* const* d_in, const int* in_sizes, int n_in,
                              void* d_out, int out_size) {
    (void)in_sizes; (void)n_in; (void)out_size;
    const float* query = (const float*)d_in[0];
    const float* key   = (const float*)d_in[1];
    const float* value = (const float*)d_in[2];
    const float* Wq = (const float*)d_in[3];
    const float* bq = (const float*)d_in[4];
    const float* Wk = (const float*)d_in[5];
    const float* bk = (const float*)d_in[6];
    const float* Wv = (const float*)d_in[7];
    const float* bv = (const float*)d_in[8];
    const float* Wo = (const float*)d_in[9];
    const float* bo = (const float*)d_in[10];
    const float* gq    = (const float*)d_in[11];
    const float* betaq = (const float*)d_in[12];
    const float* gk    = (const float*)d_in[13];
    const float* betak = (const float*)d_in[14];
    float* out = (float*)d_out;

    float *pq, *pk, *pv, *pattn;
    cudaGetSymbolAddress((void**)&pq, g_q);
    cudaGetSymbolAddress((void**)&pk, g_k);
    cudaGetSymbolAddress((void**)&pv, g_v);
    cudaGetSymbolAddress((void**)&pattn, g_attn);

    cudaFuncSetAttribute(gemm_mma_kernel,
                         cudaFuncAttributeMaxDynamicSharedMemorySize, GEMM_SMEM);

    dim3 ggrid(MTOT / BM, E_ / BN);   // (128, 8)

    gemm_mma_kernel<<<ggrid, 256, GEMM_SMEM>>>(query, Wq, bq, pq);
    ln_elu_kernel<<<MTOT, 256>>>(pq, gq, betaq);
    gemm_mma_kernel<<<ggrid, 256, GEMM_SMEM>>>(key, Wk, bk, pk);
    ln_elu_kernel<<<MTOT, 256>>>(pk, gk, betak);
    gemm_mma_kernel<<<ggrid, 256, GEMM_SMEM>>>(value, Wv, bv, pv);

    kv_kernel<<<dim3(BH_, NSPLIT), 256>>>();
    reduce_kv_kernel<<<(BH_ * D_ * D_ + BH_ * D_ + 255) / 256, 256>>>();

    attn_kernel<<<dim3(BH_, NQ_ / 64), 128>>>();

    gemm_mma_kernel<<<ggrid, 256, GEMM_SMEM>>>(pattn, Wo, bo, out);
}